// round 3
// baseline (speedup 1.0000x reference)
#include <cuda_runtime.h>
#include <cuda_bf16.h>
#include <math.h>

// Problem constants
#define BATCH 8
#define HGT 32
#define WID 32
#define DIM 768
#define NH 12
#define HD 64
#define LSEQ 1024            // HGT*WID
#define MROWS (BATCH*LSEQ)   // 8192
#define NQKV (3*DIM)         // 2304

// ---------------- scratch (static device globals; no allocation) ----------------
__device__ float g_qkv[MROWS * NQKV];          // (B,L,3*dim)
__device__ float g_q[BATCH * NH * LSEQ * HD];  // (B,nH,L,hd) rope'd
__device__ float g_k[BATCH * NH * LSEQ * HD];
__device__ float g_v[BATCH * NH * LSEQ * HD];
__device__ float g_att[MROWS * DIM];           // (B,L,dim) attention output

// ---------------- tiled NT GEMM: C[m,n] = sum_k A[m,k]*B[n,k] + bias[n] ----------
// A: (M,K) row-major, B: (N,K) row-major. M,N multiples of 64, K multiple of 32.
#define GBM 64
#define GBN 64
#define GBK 32

__global__ __launch_bounds__(256) void gemm_nt_bias(
    const float* __restrict__ A, const float* __restrict__ Bm,
    const float* __restrict__ bias, float* __restrict__ C,
    int Mdim, int Ndim, int Kdim)
{
    __shared__ float As[GBK][GBM + 4];  // row stride 68 -> float4-aligned, few conflicts
    __shared__ float Bs[GBK][GBN + 4];

    const int tid = threadIdx.x;
    const int tx = tid & 15;        // 0..15 -> n micro
    const int ty = tid >> 4;        // 0..15 -> m micro
    const int m0 = blockIdx.y * GBM;
    const int n0 = blockIdx.x * GBN;

    float acc[4][4];
#pragma unroll
    for (int i = 0; i < 4; i++)
#pragma unroll
        for (int j = 0; j < 4; j++) acc[i][j] = 0.f;

    const int lr = tid >> 3;          // 0..31 rows
    const int lc = (tid & 7) * 4;     // 0..28 cols (k)

    for (int k0 = 0; k0 < Kdim; k0 += GBK) {
        float4 a0 = *(const float4*)&A[(size_t)(m0 + lr) * Kdim + k0 + lc];
        float4 a1 = *(const float4*)&A[(size_t)(m0 + lr + 32) * Kdim + k0 + lc];
        float4 b0 = *(const float4*)&Bm[(size_t)(n0 + lr) * Kdim + k0 + lc];
        float4 b1 = *(const float4*)&Bm[(size_t)(n0 + lr + 32) * Kdim + k0 + lc];

        __syncthreads();
        As[lc + 0][lr] = a0.x; As[lc + 1][lr] = a0.y; As[lc + 2][lr] = a0.z; As[lc + 3][lr] = a0.w;
        As[lc + 0][lr + 32] = a1.x; As[lc + 1][lr + 32] = a1.y; As[lc + 2][lr + 32] = a1.z; As[lc + 3][lr + 32] = a1.w;
        Bs[lc + 0][lr] = b0.x; Bs[lc + 1][lr] = b0.y; Bs[lc + 2][lr] = b0.z; Bs[lc + 3][lr] = b0.w;
        Bs[lc + 0][lr + 32] = b1.x; Bs[lc + 1][lr + 32] = b1.y; Bs[lc + 2][lr + 32] = b1.z; Bs[lc + 3][lr + 32] = b1.w;
        __syncthreads();

#pragma unroll
        for (int kk = 0; kk < GBK; kk++) {
            float4 av = *(const float4*)&As[kk][ty * 4];
            float4 bv = *(const float4*)&Bs[kk][tx * 4];
            float a[4] = {av.x, av.y, av.z, av.w};
            float b[4] = {bv.x, bv.y, bv.z, bv.w};
#pragma unroll
            for (int i = 0; i < 4; i++)
#pragma unroll
                for (int j = 0; j < 4; j++) acc[i][j] += a[i] * b[j];
        }
    }

    float4 bb = *(const float4*)&bias[n0 + tx * 4];
    float bj[4] = {bb.x, bb.y, bb.z, bb.w};
#pragma unroll
    for (int i = 0; i < 4; i++) {
        float4 o;
        o.x = acc[i][0] + bj[0];
        o.y = acc[i][1] + bj[1];
        o.z = acc[i][2] + bj[2];
        o.w = acc[i][3] + bj[3];
        *(float4*)&C[(size_t)(m0 + ty * 4 + i) * Ndim + n0 + tx * 4] = o;
    }
}

// ---------------- split qkv + 2D axial RoPE ----------------
// one thread per (b,n,l, pair j in [0,32)); handles q,k (rope) and v (copy)
__global__ __launch_bounds__(256) void rope_split_kernel(
    const float* __restrict__ qkv,
    float* __restrict__ q, float* __restrict__ k, float* __restrict__ v)
{
    int idx = blockIdx.x * blockDim.x + threadIdx.x;
    const int TOT = BATCH * NH * LSEQ * (HD / 2);
    if (idx >= TOT) return;
    int j = idx & 31;
    int l = (idx >> 5) & (LSEQ - 1);
    int n = (idx >> 15) % NH;
    int b = idx / (32 * LSEQ * NH);

    size_t in_base = ((size_t)(b * LSEQ + l)) * NQKV + n * HD + 2 * j;
    size_t out_base = ((size_t)((b * NH + n) * LSEQ + l)) * HD + 2 * j;

    int i = j & 15;
    float pos = (j < 16) ? (float)(l & 31) : (float)(l >> 5);
    // f_i = 10000^(-i/16) ; log2(10000) = 13.287712379549449
    float f = exp2f(-(float)i * (13.287712379549449f / 16.0f));
    float ang = pos * f;
    float sn, cs;
    sincosf(ang, &sn, &cs);

    float2 qa = *(const float2*)&qkv[in_base];
    float2 ka = *(const float2*)&qkv[in_base + DIM];
    float2 va = *(const float2*)&qkv[in_base + 2 * DIM];

    float2 qo, ko;
    qo.x = qa.x * cs - qa.y * sn; qo.y = qa.x * sn + qa.y * cs;
    ko.x = ka.x * cs - ka.y * sn; ko.y = ka.x * sn + ka.y * cs;

    *(float2*)&q[out_base] = qo;
    *(float2*)&k[out_base] = ko;
    *(float2*)&v[out_base] = va;
}

// ---------------- attention ----------------
// block: 256 threads, one (b*nH) head slice x 16-query tile.
// smem: full score tile [16][1024] (stride 1032), q tile, rel biases.
#define TQ 16
#define SSTR 1032
#define QSTR 68
#define RSTR 33
#define ATTN_SMEM_FLOATS (TQ*SSTR + TQ*QSTR + 2*TQ*RSTR + TQ)
#define ATTN_SMEM_BYTES (ATTN_SMEM_FLOATS * 4)

__global__ __launch_bounds__(256) void attn_kernel(
    const float* __restrict__ Q, const float* __restrict__ K,
    const float* __restrict__ V, const float* __restrict__ rph,
    const float* __restrict__ rpw, float* __restrict__ Out)
{
    extern __shared__ float sm[];
    float* sc = sm;                           // TQ * SSTR
    float* qs = sc + TQ * SSTR;               // TQ * QSTR
    float* rh = qs + TQ * QSTR;               // TQ * RSTR
    float* rw = rh + TQ * RSTR;               // TQ * RSTR
    float* ssum = rw + TQ * RSTR;             // TQ

    const int tid = threadIdx.x;
    const int bn = blockIdx.y;                // b*NH + n
    const int b = bn / NH, n = bn % NH;
    const int q0 = blockIdx.x * TQ;

    const float* Qb = Q + ((size_t)bn * LSEQ + q0) * HD;
    const float* Kb = K + (size_t)bn * LSEQ * HD;
    const float* Vb = V + (size_t)bn * LSEQ * HD;

    // load 16x64 q tile (contiguous 1024 floats)
    {
        float4 t4 = ((const float4*)Qb)[tid];
        int qq = tid >> 4;
        int dd = (tid & 15) * 4;
        *(float4*)&qs[qq * QSTR + dd] = t4;
    }
    __syncthreads();

    // rel position biases: 16 queries x (32 h + 32 w) dots of length 64
    for (int u = tid; u < TQ * 64; u += 256) {
        int qq = u >> 6, j = u & 63;
        int lq = q0 + qq;
        int ridx;
        const float* rp;
        if (j < 32) { ridx = (lq >> 5) - j + (HGT - 1); rp = rph; }
        else        { ridx = (lq & 31) - (j - 32) + (WID - 1); rp = rpw; }
        const float* rr = rp + ridx * HD;
        float acc = 0.f;
#pragma unroll
        for (int d = 0; d < HD; d += 4) {
            float4 r4 = *(const float4*)&rr[d];
            float4 q4 = *(const float4*)&qs[qq * QSTR + d];
            acc += q4.x * r4.x + q4.y * r4.y + q4.z * r4.z + q4.w * r4.w;
        }
        if (j < 32) rh[qq * RSTR + j] = acc;
        else        rw[qq * RSTR + (j - 32)] = acc;
    }
    __syncthreads();

    // scores: thread = (q = tid&15, key offset = tid>>4); loop key tiles of 16
    {
        const int qq = tid & 15;
        const int dk = tid >> 4;
        const float rscale = 0.125f; // 1/sqrt(64)
        for (int k0 = 0; k0 < LSEQ; k0 += 16) {
            int kk = k0 + dk;
            const float* Kr = Kb + (size_t)kk * HD;
            float acc = 0.f;
#pragma unroll
            for (int d = 0; d < HD; d += 4) {
                float4 k4 = *(const float4*)&Kr[d];
                float4 q4 = *(const float4*)&qs[qq * QSTR + d];
                acc += q4.x * k4.x + q4.y * k4.y + q4.z * k4.z + q4.w * k4.w;
            }
            sc[qq * SSTR + kk] = acc * rscale + rh[qq * RSTR + (kk >> 5)] + rw[qq * RSTR + (kk & 31)];
        }
    }
    __syncthreads();

    // softmax per row (unnormalized exp; keep row sums)
    {
        const int wid = tid >> 5, lane = tid & 31;
        for (int r = wid; r < TQ; r += 8) {
            float m = -1e30f;
            for (int kk = lane; kk < LSEQ; kk += 32) m = fmaxf(m, sc[r * SSTR + kk]);
#pragma unroll
            for (int o = 16; o; o >>= 1) m = fmaxf(m, __shfl_xor_sync(0xffffffffu, m, o));
            float s = 0.f;
            for (int kk = lane; kk < LSEQ; kk += 32) {
                float e = expf(sc[r * SSTR + kk] - m);
                sc[r * SSTR + kk] = e;
                s += e;
            }
#pragma unroll
            for (int o = 16; o; o >>= 1) s += __shfl_xor_sync(0xffffffffu, s, o);
            if (lane == 0) ssum[r] = s;
        }
    }
    __syncthreads();

    // AV: thread = (d = tid&63, key-group g = tid>>6 covering 256 keys)
    {
        const int d = tid & 63;
        const int g = tid >> 6;
        float acc[TQ];
#pragma unroll
        for (int i = 0; i < TQ; i++) acc[i] = 0.f;
        const int kbeg = g * 256, kend = kbeg + 256;
        for (int kk = kbeg; kk < kend; kk++) {
            float vv = Vb[(size_t)kk * HD + d];
#pragma unroll
            for (int i = 0; i < TQ; i++) acc[i] += sc[i * SSTR + kk] * vv;
        }
        __syncthreads();
        // reduce 4 key-groups via smem (reuse score region)
        float* part = sm; // 4*16*64 = 4096 floats, fits inside sc region
#pragma unroll
        for (int i = 0; i < TQ; i++) part[(g * TQ + i) * HD + d] = acc[i];
        __syncthreads();
        for (int u = tid; u < TQ * HD; u += 256) {
            int qq = u >> 6, dd = u & 63;
            float s = part[(0 * TQ + qq) * HD + dd] + part[(1 * TQ + qq) * HD + dd]
                    + part[(2 * TQ + qq) * HD + dd] + part[(3 * TQ + qq) * HD + dd];
            s /= ssum[qq];
            int l = q0 + qq;
            Out[((size_t)b * LSEQ + l) * DIM + n * HD + dd] = s;
        }
    }
}

// ---------------- launch ----------------
extern "C" void kernel_launch(void* const* d_in, const int* in_sizes, int n_in,
                              void* d_out, int out_size)
{
    const float* x      = (const float*)d_in[0];
    const float* qkv_w  = (const float*)d_in[1];
    const float* qkv_b  = (const float*)d_in[2];
    const float* proj_w = (const float*)d_in[3];
    const float* proj_b = (const float*)d_in[4];
    const float* rph    = (const float*)d_in[5];
    const float* rpw    = (const float*)d_in[6];
    float* out = (float*)d_out;

    float *p_qkv, *p_q, *p_k, *p_v, *p_att;
    cudaGetSymbolAddress((void**)&p_qkv, g_qkv);
    cudaGetSymbolAddress((void**)&p_q, g_q);
    cudaGetSymbolAddress((void**)&p_k, g_k);
    cudaGetSymbolAddress((void**)&p_v, g_v);
    cudaGetSymbolAddress((void**)&p_att, g_att);

    // 1) QKV GEMM: (8192x768) @ (2304x768)^T + b
    gemm_nt_bias<<<dim3(NQKV / GBN, MROWS / GBM), 256>>>(
        x, qkv_w, qkv_b, p_qkv, MROWS, NQKV, DIM);

    // 2) split + rope
    {
        const int TOT = BATCH * NH * LSEQ * (HD / 2);
        rope_split_kernel<<<(TOT + 255) / 256, 256>>>(p_qkv, p_q, p_k, p_v);
    }

    // 3) attention
    cudaFuncSetAttribute(attn_kernel, cudaFuncAttributeMaxDynamicSharedMemorySize,
                         ATTN_SMEM_BYTES);
    attn_kernel<<<dim3(LSEQ / TQ, BATCH * NH), 256, ATTN_SMEM_BYTES>>>(
        p_q, p_k, p_v, rph, rpw, p_att);

    // 4) output projection: (8192x768) @ (768x768)^T + b
    gemm_nt_bias<<<dim3(DIM / GBN, MROWS / GBM), 256>>>(
        p_att, proj_w, proj_b, out, MROWS, DIM, DIM);
}